// round 15
// baseline (speedup 1.0000x reference)
#include <cuda_runtime.h>

#define NT 1096
#define NS 2048
#define NH 16
#define NL (NS*NH)
#define UF 8                 // NT = 8 * 137
#define SPB 2                // sites per block (32 threads) -> 1024 blocks, ~7/SM balanced
#define RS 1104              // padded smem row stride (floats): covers NT+8 overrun, 16B-aligned

__global__ __launch_bounds__(32)
void waternet_kernel(const float* __restrict__ P, const float* __restrict__ T,
                     const float* __restrict__ w_i, const float* __restrict__ w_o,
                     const float* __restrict__ w_l, const float* __restrict__ w_s,
                     float* __restrict__ Q, float* __restrict__ H, float* __restrict__ S)
{
    __shared__ float sP[SPB * RS];
    __shared__ float sT[SPB * RS];

    const int tid = threadIdx.x;
    const int s0  = blockIdx.x * SPB;

    // ── Fill: stage this block's 2 sites' full P/T series into smem ──
    for (int t = tid; t < NT; t += 32) {
        const float2 vp = *(const float2*)(P + (size_t)t * NS + s0);
        const float2 vt = *(const float2*)(T + (size_t)t * NS + s0);
        sP[0 * RS + t] = vp.x; sP[1 * RS + t] = vp.y;
        sT[0 * RS + t] = vt.x; sT[1 * RS + t] = vt.y;
    }
    __syncthreads();

    const int lsite = tid >> 4;          // 0..1
    const int h     = tid & 15;
    const int site  = s0 + lsite;

    // Gates (once per thread)
    const float melt = expf(w_s[h]) + 1.0f;
    const float gi   = 1.0f / (1.0f + expf(-w_i[h]));
    const float gl   = 1.0f / (1.0f + expf(-w_l[h]));
    float wmax = w_o[0];
    #pragma unroll
    for (int i = 1; i < NH; ++i) wmax = fmaxf(wmax, w_o[i]);
    float denom = 0.0f;
    #pragma unroll
    for (int i = 0; i < NH; ++i) denom += expf(w_o[i] - wmax);
    const float a = expf(w_o[h] - wmax) / denom;

    const float alpha = 1.0f - gl;
    const float gax   = alpha * gi;       // hs' = alpha*hs + gax*x
    const float ch    = a * gl / alpha;   // q*a = hs' * ch

    float s  = 0.0f;
    float hs = 0.0f;

    const float4* myP4 = (const float4*)(sP + lsite * RS);
    const float4* myT4 = (const float4*)(sT + lsite * RS);

    // 32-bit element offsets (all outputs < 150MB, fits easily)
    float* Hp = H + (unsigned)(site * NH + h);
    float* Sp = S + (unsigned)(site * NH + h);

    const bool b3 = (h & 8) != 0;
    const bool b2 = (h & 4) != 0;
    const bool b1 = (h & 2) != 0;
    const bool qlane = (h & 1) == 0;
    const int  qidx  = h >> 1;

    // One-group-ahead register prefetch from smem (branch-free; padding absorbs overrun)
    float4 pb0 = myP4[0], pb1 = myP4[1];
    float4 tb0 = myT4[0], tb1 = myT4[1];

    unsigned offHS = 0;                          // (t0+i)*NL, 32-bit
    unsigned offQ  = (unsigned)(qidx * NS + site);

    for (int t0 = 0; t0 < NT; t0 += UF) {
        const float4 pA = pb0, pB = pb1, tA = tb0, tB = tb1;
        const int nb = (t0 + UF) >> 2;
        pb0 = myP4[nb]; pb1 = myP4[nb + 1];
        tb0 = myT4[nb]; tb1 = myT4[nb + 1];

        float qa[UF];
        #pragma unroll
        for (int i = 0; i < UF; ++i) {
            const float Pk = (i < 4) ? ((i == 0) ? pA.x : (i == 1) ? pA.y : (i == 2) ? pA.z : pA.w)
                                     : ((i == 4) ? pB.x : (i == 5) ? pB.y : (i == 6) ? pB.z : pB.w);
            const float Tk = (i < 4) ? ((i == 0) ? tA.x : (i == 1) ? tA.y : (i == 2) ? tA.z : tA.w)
                                     : ((i == 4) ? tB.x : (i == 5) ? tB.y : (i == 6) ? tB.z : tB.w);

            const float m    = fminf(fmaxf(Tk, 0.0f) * melt, s);
            const float pin  = (Tk < 0.0f) ? Pk : 0.0f;
            const float rain = (Tk > 0.0f) ? Pk : 0.0f;
            s  = (s - m) + pin;
            hs = alpha * hs + gax * (rain + m);

            // Streaming stores: write-once data, evict-first in L2.
            __stcs(Hp + offHS, hs);
            __stcs(Sp + offHS, s);
            offHS += NL;
            qa[i] = hs * ch;
        }

        // Value-split reduction: 8 values over 16 lanes in 8 SHFLs (validated).
        #pragma unroll
        for (int i = 0; i < 4; ++i) {
            const float send = b3 ? qa[i] : qa[i + 4];
            const float recv = __shfl_xor_sync(0xffffffffu, send, 8);
            const float keep = b3 ? qa[i + 4] : qa[i];
            qa[i] = keep + recv;
        }
        #pragma unroll
        for (int i = 0; i < 2; ++i) {
            const float send = b2 ? qa[i] : qa[i + 2];
            const float recv = __shfl_xor_sync(0xffffffffu, send, 4);
            const float keep = b2 ? qa[i + 2] : qa[i];
            qa[i] = keep + recv;
        }
        {
            const float send = b1 ? qa[0] : qa[1];
            const float recv = __shfl_xor_sync(0xffffffffu, send, 2);
            const float keep = b1 ? qa[1] : qa[0];
            qa[0] = keep + recv;
        }
        qa[0] += __shfl_xor_sync(0xffffffffu, qa[0], 1);

        if (qlane) __stcs(Q + offQ, qa[0]);
        offQ += (unsigned)(UF * NS);
    }
}

extern "C" void kernel_launch(void* const* d_in, const int* in_sizes, int n_in,
                              void* d_out, int out_size) {
    const float* P   = (const float*)d_in[0];
    const float* T   = (const float*)d_in[1];
    const float* w_i = (const float*)d_in[2];
    const float* w_o = (const float*)d_in[3];
    const float* w_l = (const float*)d_in[4];
    const float* w_s = (const float*)d_in[5];

    float* out = (float*)d_out;
    float* Q = out;                                           // [NT, NS]
    float* H = out + (size_t)NT * NS;                         // [NT, NS, NH]
    float* S = out + (size_t)NT * NS + (size_t)NT * NS * NH;  // [NT, NS, NH]

    waternet_kernel<<<NS / SPB, 32>>>(P, T, w_i, w_o, w_l, w_s, Q, H, S);  // 1024 blocks
}

// round 16
// speedup vs baseline: 1.7435x; 1.7435x over previous
#include <cuda_runtime.h>

#define NT 1096
#define NS 2048
#define NH 16
#define NL (NS*NH)
#define UF 8
#define SPB 8                // sites per block; 64 threads = 8 sites x 8 h-pairs
#define PH0 552              // phase-0 steps (69 groups); phase-1 = 544 (68 groups)
#define RS 568               // padded smem row stride (floats): >=552+8 overrun, bank-spread

__global__ __launch_bounds__(64)
void waternet_kernel(const float* __restrict__ P, const float* __restrict__ T,
                     const float* __restrict__ w_i, const float* __restrict__ w_o,
                     const float* __restrict__ w_l, const float* __restrict__ w_s,
                     float* __restrict__ Q, float* __restrict__ H, float* __restrict__ S)
{
    __shared__ float sP[SPB * RS];
    __shared__ float sT[SPB * RS];

    const int tid   = threadIdx.x;
    const int s0    = blockIdx.x * SPB;
    const int lsite = tid >> 3;            // 0..7
    const int hp    = tid & 7;             // h-pair: handles h0=2hp, h1=2hp+1
    const int site  = s0 + lsite;
    const int h0    = hp * 2;
    const int h1    = h0 + 1;

    // Gates for both h lanes
    const float melt0 = expf(w_s[h0]) + 1.0f;
    const float melt1 = expf(w_s[h1]) + 1.0f;
    const float gi0   = 1.0f / (1.0f + expf(-w_i[h0]));
    const float gi1   = 1.0f / (1.0f + expf(-w_i[h1]));
    const float gl0   = 1.0f / (1.0f + expf(-w_l[h0]));
    const float gl1   = 1.0f / (1.0f + expf(-w_l[h1]));
    float wmax = w_o[0];
    #pragma unroll
    for (int i = 1; i < NH; ++i) wmax = fmaxf(wmax, w_o[i]);
    float denom = 0.0f;
    #pragma unroll
    for (int i = 0; i < NH; ++i) denom += expf(w_o[i] - wmax);
    const float a0 = expf(w_o[h0] - wmax) / denom;
    const float a1 = expf(w_o[h1] - wmax) / denom;

    const float alpha0 = 1.0f - gl0, alpha1 = 1.0f - gl1;
    const float gax0 = alpha0 * gi0,  gax1 = alpha1 * gi1;
    const float ch0  = a0 * gl0 / alpha0;
    const float ch1  = a1 * gl1 / alpha1;

    float s0v = 0.0f, s1v = 0.0f, hs0 = 0.0f, hs1 = 0.0f;

    // H/S base: thread stores (h0,h1) as one float2
    float2* Hp = (float2*)(H + (unsigned)(site * NH + h0));
    float2* Sp = (float2*)(S + (unsigned)(site * NH + h0));
    const unsigned HS_STRIDE2 = NL / 2;                 // float2 stride per t

    const bool b2 = (hp & 4) != 0;
    const bool b1 = (hp & 2) != 0;
    const bool b0 = (hp & 1) != 0;

    const float4* myP4 = (const float4*)(sP + lsite * RS);
    const float4* myT4 = (const float4*)(sT + lsite * RS);

    int tbase = 0;                                      // global t at phase start
    #pragma unroll
    for (int ph = 0; ph < 2; ++ph) {
        const int plen = ph ? (NT - PH0) : PH0;         // 552 / 544

        // ── Fill: stage this phase's series for 8 sites (float4 rows) ──
        __syncthreads();                                // protect smem reuse
        for (int t = tid; t < plen; t += 64) {
            const float* Pr = P + (size_t)(tbase + t) * NS + s0;
            const float* Tr = T + (size_t)(tbase + t) * NS + s0;
            const float4 vp0 = *(const float4*)(Pr);
            const float4 vp1 = *(const float4*)(Pr + 4);
            const float4 vt0 = *(const float4*)(Tr);
            const float4 vt1 = *(const float4*)(Tr + 4);
            sP[0*RS+t]=vp0.x; sP[1*RS+t]=vp0.y; sP[2*RS+t]=vp0.z; sP[3*RS+t]=vp0.w;
            sP[4*RS+t]=vp1.x; sP[5*RS+t]=vp1.y; sP[6*RS+t]=vp1.z; sP[7*RS+t]=vp1.w;
            sT[0*RS+t]=vt0.x; sT[1*RS+t]=vt0.y; sT[2*RS+t]=vt0.z; sT[3*RS+t]=vt0.w;
            sT[4*RS+t]=vt1.x; sT[5*RS+t]=vt1.y; sT[6*RS+t]=vt1.z; sT[7*RS+t]=vt1.w;
        }
        __syncthreads();

        float4 pb0 = myP4[0], pb1 = myP4[1];
        float4 tb0 = myT4[0], tb1 = myT4[1];

        unsigned offHS = (unsigned)tbase * HS_STRIDE2;
        unsigned offQ  = (unsigned)((tbase + hp) * NS + site);

        for (int tl = 0; tl < plen; tl += UF) {
            const float4 pA = pb0, pB = pb1, tA = tb0, tB = tb1;
            const int nb = (tl + UF) >> 2;              // padding absorbs overrun
            pb0 = myP4[nb]; pb1 = myP4[nb + 1];
            tb0 = myT4[nb]; tb1 = myT4[nb + 1];

            float qa[UF];
            #pragma unroll
            for (int i = 0; i < UF; ++i) {
                const float Pk = (i < 4) ? ((i==0)?pA.x:(i==1)?pA.y:(i==2)?pA.z:pA.w)
                                         : ((i==4)?pB.x:(i==5)?pB.y:(i==6)?pB.z:pB.w);
                const float Tk = (i < 4) ? ((i==0)?tA.x:(i==1)?tA.y:(i==2)?tA.z:tA.w)
                                         : ((i==4)?tB.x:(i==5)?tB.y:(i==6)?tB.z:tB.w);

                const float warm = fmaxf(Tk, 0.0f);
                const float pin  = (Tk < 0.0f) ? Pk : 0.0f;
                const float rain = (Tk > 0.0f) ? Pk : 0.0f;

                const float m0 = fminf(warm * melt0, s0v);
                s0v = (s0v - m0) + pin;
                hs0 = alpha0 * hs0 + gax0 * (rain + m0);

                const float m1 = fminf(warm * melt1, s1v);
                s1v = (s1v - m1) + pin;
                hs1 = alpha1 * hs1 + gax1 * (rain + m1);

                __stcs(Hp + offHS, make_float2(hs0, hs1));
                __stcs(Sp + offHS, make_float2(s0v, s1v));
                offHS += HS_STRIDE2;

                qa[i] = hs0 * ch0 + hs1 * ch1;
            }

            // Value-split: 8 values over the 8-lane site group in 7 SHFLs.
            // After the tree, lane hp holds the full sum for timestep tl+hp.
            #pragma unroll
            for (int i = 0; i < 4; ++i) {
                const float send = b2 ? qa[i] : qa[i + 4];
                const float recv = __shfl_xor_sync(0xffffffffu, send, 4);
                const float keep = b2 ? qa[i + 4] : qa[i];
                qa[i] = keep + recv;
            }
            #pragma unroll
            for (int i = 0; i < 2; ++i) {
                const float send = b1 ? qa[i] : qa[i + 2];
                const float recv = __shfl_xor_sync(0xffffffffu, send, 2);
                const float keep = b1 ? qa[i + 2] : qa[i];
                qa[i] = keep + recv;
            }
            {
                const float send = b0 ? qa[0] : qa[1];
                const float recv = __shfl_xor_sync(0xffffffffu, send, 1);
                const float keep = b0 ? qa[1] : qa[0];
                qa[0] = keep + recv;
            }

            __stcs(Q + offQ, qa[0]);                    // every lane: one t-row
            offQ += (unsigned)(UF * NS);
        }
        tbase += plen;
    }
}

extern "C" void kernel_launch(void* const* d_in, const int* in_sizes, int n_in,
                              void* d_out, int out_size) {
    const float* P   = (const float*)d_in[0];
    const float* T   = (const float*)d_in[1];
    const float* w_i = (const float*)d_in[2];
    const float* w_o = (const float*)d_in[3];
    const float* w_l = (const float*)d_in[4];
    const float* w_s = (const float*)d_in[5];

    float* out = (float*)d_out;
    float* Q = out;                                           // [NT, NS]
    float* H = out + (size_t)NT * NS;                         // [NT, NS, NH]
    float* S = out + (size_t)NT * NS + (size_t)NT * NS * NH;  // [NT, NS, NH]

    waternet_kernel<<<NS / SPB, 64>>>(P, T, w_i, w_o, w_l, w_s, Q, H, S);  // 256 blocks
}